// round 16
// baseline (speedup 1.0000x reference)
#include <cuda_runtime.h>
#include <cuda_fp16.h>
#include <cstdint>

#define N_IMG 8192
#define N_TXT 8192
#define DIM   1024
#define HDIM  1024

// ---------------------------------------------------------------------------
// Device scratch (no allocations allowed)
// ---------------------------------------------------------------------------
__device__ __align__(1024) __half g_img16[(size_t)N_IMG * DIM];
__device__ __align__(1024) __half g_txt16[(size_t)N_TXT * DIM];
__device__ __align__(1024) __half g_wqT16[(size_t)DIM * HDIM];     // Wq^T [D,H]
__device__ __align__(1024) __half g_wkT16[(size_t)DIM * HDIM];     // Wk^T [D,H]
__device__ __align__(1024) __half g_m1t16[(size_t)DIM * DIM];      // (Wq^T Wk)^T
__device__ __align__(1024) __half g_wv16 [(size_t)DIM * DIM];      // fp16 WV
__device__ __align__(1024) __half g_q16 [(size_t)N_IMG * HDIM];    // A2 = img @ M1
__device__ __align__(1024) __half g_vt16[(size_t)DIM * N_TXT];
__device__ __align__(1024) __half g_p16 [(size_t)N_IMG * N_TXT];   // 128 MB
__device__ __align__(1024) float  g_rowsum[N_IMG];

// exp constants: exp(s*0.03125 - 8) = exp2(acc*c1 + c2)
#define EXP_C1 0.04508422f      // 0.03125 * log2(e)
#define EXP_C2 -11.54156036f    // -8 * log2(e)

// ---------------------------------------------------------------------------
// Portable PTX helpers
// ---------------------------------------------------------------------------
__device__ __forceinline__ uint32_t smem_to_u32(const void* p) {
    uint32_t a;
    asm("{ .reg .u64 t; cvta.to.shared.u64 t, %1; cvt.u32.u64 %0, t; }" : "=r"(a) : "l"(p));
    return a;
}
__device__ __forceinline__ void ldmatrix_x4(uint32_t* r, uint32_t addr) {
    asm volatile("ldmatrix.sync.aligned.m8n8.x4.shared.b16 {%0,%1,%2,%3}, [%4];"
        : "=r"(r[0]), "=r"(r[1]), "=r"(r[2]), "=r"(r[3]) : "r"(addr));
}
__device__ __forceinline__ void mma_fp16(float* c, const uint32_t* a, uint32_t b0, uint32_t b1) {
    asm volatile("mma.sync.aligned.m16n8k16.row.col.f32.f16.f16.f32 "
        "{%0,%1,%2,%3}, {%4,%5,%6,%7}, {%8,%9}, {%0,%1,%2,%3};"
        : "+f"(c[0]), "+f"(c[1]), "+f"(c[2]), "+f"(c[3])
        : "r"(a[0]), "r"(a[1]), "r"(a[2]), "r"(a[3]), "r"(b0), "r"(b1));
}
#define CP_ASYNC16(dst, src) \
    asm volatile("cp.async.cg.shared.global [%0], [%1], 16;" :: "r"(dst), "l"(src) : "memory")
#define CP_COMMIT() asm volatile("cp.async.commit_group;" ::: "memory")
#define CP_WAIT1()  asm volatile("cp.async.wait_group 1;" ::: "memory")

// ===========================================================================
// Tile loaders (K-major fp16, 64 cols = 128 B/row, swizzle c ^= r&7)
// ===========================================================================
__device__ __forceinline__ void load_tile64h(uint32_t dst, const __half* __restrict__ src,
                                             int ldK, int tid) {
#pragma unroll
    for (int i = 0; i < 4; i++) {
        int idx = tid + i * 256;
        int r = idx >> 3, c = idx & 7;
        int sc = c ^ (r & 7);
        CP_ASYNC16(dst + r * 128 + (sc << 4), src + (size_t)r * ldK + c * 8);
    }
}
__device__ __forceinline__ void load_tile64x64h(uint32_t dst, const __half* __restrict__ src,
                                                int ldK, int tid) {
#pragma unroll
    for (int i = 0; i < 2; i++) {
        int idx = tid + i * 256;
        int r = idx >> 3, c = idx & 7;
        int sc = c ^ (r & 7);
        CP_ASYNC16(dst + r * 128 + (sc << 4), src + (size_t)r * ldK + c * 8);
    }
}

// ===========================================================================
// Kernel A: 128x128 fp16 GEMM (C fp16) — M1 only (tiny)
// ===========================================================================
constexpr int H_TILE = 16384;
constexpr int H_OFF_A = 0, H_OFF_B = H_TILE;
constexpr int H_STG = 2 * H_TILE;
constexpr int H_NSTAGE = 3;
constexpr int H_SMEM = H_NSTAGE * H_STG;     // 96 KB

__global__ void __launch_bounds__(256, 1)
hgemm128(const __half* __restrict__ A, const __half* __restrict__ B,
         __half* __restrict__ Ch, int M, int N, int K)
{
    extern __shared__ __align__(1024) char smem[];
    const uint32_t sb = smem_to_u32(smem);
    const int tid  = threadIdx.x;
    const int lane = tid & 31;
    const int wid  = tid >> 5;
    const int wm   = wid & 1;
    const int wn   = wid >> 1;
    const int m0   = blockIdx.y * 128, n0 = blockIdx.x * 128;

    const __half* Ar = A + (size_t)m0 * K;
    const __half* Br = B + (size_t)n0 * K;

    float acc[4][4][4];
#pragma unroll
    for (int i = 0; i < 4; i++)
#pragma unroll
        for (int j = 0; j < 4; j++)
#pragma unroll
            for (int t = 0; t < 4; t++) acc[i][j][t] = 0.f;

    const int NK = K >> 6;

#pragma unroll
    for (int i = 0; i < H_NSTAGE - 1; i++) {
        if (i < NK) {
            uint32_t st = sb + i * H_STG;
            int ko = i * 64;
            load_tile64h(st + H_OFF_A, Ar + ko, K, tid);
            load_tile64h(st + H_OFF_B, Br + ko, K, tid);
        }
        CP_COMMIT();
    }

    const int lr = lane & 15;
    const int lc = lane >> 4;

    for (int k = 0; k < NK; k++) {
        CP_WAIT1();
        __syncthreads();

        int kn = k + H_NSTAGE - 1;
        if (kn < NK) {
            uint32_t st = sb + (kn % H_NSTAGE) * H_STG;
            int ko = kn * 64;
            load_tile64h(st + H_OFF_A, Ar + ko, K, tid);
            load_tile64h(st + H_OFF_B, Br + ko, K, tid);
        }
        CP_COMMIT();

        const uint32_t s = sb + (k % H_NSTAGE) * H_STG;
#pragma unroll
        for (int ks = 0; ks < 4; ks++) {
            uint32_t af[4][4], bfr[2][4];
#pragma unroll
            for (int mi = 0; mi < 4; mi++) {
                int r = wm * 64 + mi * 16 + lr;
                int c = ks * 2 + lc;
                int sc = c ^ (r & 7);
                ldmatrix_x4(af[mi], s + H_OFF_A + r * 128 + (sc << 4));
            }
#pragma unroll
            for (int nj = 0; nj < 2; nj++) {
                int r = wn * 32 + nj * 16 + lr;
                int c = ks * 2 + lc;
                int sc = c ^ (r & 7);
                ldmatrix_x4(bfr[nj], s + H_OFF_B + r * 128 + (sc << 4));
            }
#pragma unroll
            for (int mi = 0; mi < 4; mi++)
#pragma unroll
                for (int ni = 0; ni < 4; ni++) {
                    int nj = ni >> 1, hl = ni & 1;
                    mma_fp16(acc[mi][ni], af[mi], bfr[nj][hl], bfr[nj][2 + hl]);
                }
        }
    }

    const int er = (lane >> 2);
    const int ec = (lane & 3) * 2;
#pragma unroll
    for (int mi = 0; mi < 4; mi++)
#pragma unroll
        for (int ni = 0; ni < 4; ni++) {
            int row = m0 + wm * 64 + mi * 16 + er;
            int col = n0 + wn * 32 + ni * 8 + ec;
#pragma unroll
            for (int h = 0; h < 2; h++) {
                size_t off = (size_t)(row + 8 * h) * N + col;
                *reinterpret_cast<__half2*>(Ch + off) =
                    __floats2half2_rn(acc[mi][ni][2 * h], acc[mi][ni][2 * h + 1]);
            }
        }
}

// ===========================================================================
// Kernel B: 64x128 fp16 GEMM, 4 CTAs/SM, 2 stages (rolling smem offsets)
//   MODE 1: C fp16 (A2, Vt);  MODE 2: exp epilogue (QK);  MODE 3: /rowsum (PV)
// ===========================================================================
constexpr int S64_OFF_A = 0, S64_OFF_B = 8192;    // A 8 KB, B 16 KB
constexpr int S64_STG = 24576;
constexpr int S64_NSTAGE = 2;
constexpr int S64_SMEM = S64_NSTAGE * S64_STG;    // 48 KB (4 CTAs: 192 KB/SM)

template <int MODE>
__global__ void __launch_bounds__(256, 4)
hgemm64(const __half* __restrict__ A, const __half* __restrict__ B,
        float* __restrict__ Cf, __half* __restrict__ Ch,
        float* __restrict__ rowsum, int M, int N, int K)
{
    extern __shared__ __align__(1024) char smem[];
    const uint32_t sb = smem_to_u32(smem);
    const int tid  = threadIdx.x;
    const int lane = tid & 31;
    const int wid  = tid >> 5;
    const int wm   = wid & 1;     // 2 warp rows (32 rows each)
    const int wn   = wid >> 1;    // 4 warp cols (32 cols each)
    const int m0   = blockIdx.y * 64, n0 = blockIdx.x * 128;

    // rolling global pointers (advance by 64 each chunk)
    const __half* Aw = A + (size_t)m0 * K;
    const __half* Bw = B + (size_t)n0 * K;

    float acc[2][4][4];
#pragma unroll
    for (int i = 0; i < 2; i++)
#pragma unroll
        for (int j = 0; j < 4; j++)
#pragma unroll
            for (int t = 0; t < 4; t++) acc[i][j][t] = 0.f;

    const int NK = K >> 6;

    // prologue: stage 0 in flight
    {
        load_tile64x64h(sb + S64_OFF_A, Aw, K, tid);
        load_tile64h(sb + S64_OFF_B, Bw, K, tid);
        Aw += 64; Bw += 64;
        CP_COMMIT();
    }

    const int lr = lane & 15;
    const int lc = lane >> 4;
    const uint32_t arow0 = (uint32_t)(wm * 32 + lr) * 128 + S64_OFF_A;
    const uint32_t brow0 = (uint32_t)(wn * 32 + lr) * 128 + S64_OFF_B;
    const int arb0 = (wm * 32 + lr) & 7;
    const int brb0 = (wn * 32 + lr) & 7;

    // rolling smem stage offsets (2 stages)
    uint32_t rd = sb;
    uint32_t wr = sb + S64_STG;
    const uint32_t send = sb + 2 * S64_STG;

    for (int k = 0; k < NK; k++) {
        asm volatile("cp.async.wait_group 0;" ::: "memory");
        __syncthreads();

        if (k + 1 < NK) {
            load_tile64x64h(wr + S64_OFF_A, Aw, K, tid);
            load_tile64h(wr + S64_OFF_B, Bw, K, tid);
            Aw += 64; Bw += 64;
        }
        CP_COMMIT();
        wr += S64_STG; if (wr == send) wr = sb;

        const uint32_t sa = rd + arow0;
        const uint32_t sbb = rd + brow0;
#pragma unroll
        for (int ks = 0; ks < 4; ks++) {
            const int c = ks * 2 + lc;
            uint32_t af[2][4], bfr[2][4];
            ldmatrix_x4(af[0], sa + ((c ^ arb0) << 4));
            ldmatrix_x4(af[1], sa + 16 * 128 + ((c ^ arb0) << 4));
            ldmatrix_x4(bfr[0], sbb + ((c ^ brb0) << 4));
            ldmatrix_x4(bfr[1], sbb + 16 * 128 + ((c ^ brb0) << 4));
#pragma unroll
            for (int mi = 0; mi < 2; mi++)
#pragma unroll
                for (int ni = 0; ni < 4; ni++) {
                    int nj = ni >> 1, hl = ni & 1;
                    mma_fp16(acc[mi][ni], af[mi], bfr[nj][hl], bfr[nj][2 + hl]);
                }
        }
        rd += S64_STG; if (rd == send) rd = sb;
    }

    const int er = (lane >> 2);
    const int ec = (lane & 3) * 2;
#pragma unroll
    for (int mi = 0; mi < 2; mi++) {
        float rsum[2] = {0.f, 0.f};
        float rinv[2];
        if (MODE == 3) {
            rinv[0] = 1.0f / rowsum[m0 + wm * 32 + mi * 16 + er];
            rinv[1] = 1.0f / rowsum[m0 + wm * 32 + mi * 16 + er + 8];
        }
#pragma unroll
        for (int ni = 0; ni < 4; ni++) {
            int row = m0 + wm * 32 + mi * 16 + er;
            int col = n0 + wn * 32 + ni * 8 + ec;
#pragma unroll
            for (int h = 0; h < 2; h++) {
                float v0 = acc[mi][ni][2 * h + 0];
                float v1 = acc[mi][ni][2 * h + 1];
                size_t off = (size_t)(row + 8 * h) * N + col;
                if (MODE == 1) {
                    *reinterpret_cast<__half2*>(Ch + off) = __floats2half2_rn(v0, v1);
                } else if (MODE == 2) {
                    float e0 = exp2f(fmaf(v0, EXP_C1, EXP_C2));
                    float e1 = exp2f(fmaf(v1, EXP_C1, EXP_C2));
                    *reinterpret_cast<__half2*>(Ch + off) = __floats2half2_rn(e0, e1);
                    rsum[h] += e0 + e1;
                } else {   // MODE 3
                    *reinterpret_cast<float2*>(Cf + off) =
                        make_float2(v0 * rinv[h], v1 * rinv[h]);
                }
            }
        }
        if (MODE == 2) {
#pragma unroll
            for (int h = 0; h < 2; h++) {
                float v = rsum[h];
                v += __shfl_xor_sync(0xFFFFFFFFu, v, 1);
                v += __shfl_xor_sync(0xFFFFFFFFu, v, 2);
                if ((lane & 3) == 0)
                    atomicAdd(&rowsum[m0 + wm * 32 + mi * 16 + er + 8 * h], v);
            }
        }
    }
}

// ---------------------------------------------------------------------------
// img fp32->fp16 + rowsum zeroing
// ---------------------------------------------------------------------------
constexpr int CN_IMG = N_IMG * DIM / 4;
constexpr int CN_RS  = N_IMG / 4;
constexpr int CN_MAIN = CN_IMG + CN_RS;

__global__ void __launch_bounds__(256)
conv_img_k(const float4* __restrict__ img, __half* __restrict__ img16,
           float4* __restrict__ rowsum)
{
    int i = blockIdx.x * blockDim.x + threadIdx.x;
    if (i < CN_IMG) {
        float4 v = img[i];
        __half2* p = reinterpret_cast<__half2*>(img16 + (size_t)i * 4);
        p[0] = __floats2half2_rn(v.x, v.y);
        p[1] = __floats2half2_rn(v.z, v.w);
    } else if (i - CN_IMG < CN_RS) {
        rowsum[i - CN_IMG] = make_float4(0.f, 0.f, 0.f, 0.f);
    }
}

__global__ void __launch_bounds__(256)
conv16_k(const float4* __restrict__ x, __half* __restrict__ y, int n4)
{
    int i = blockIdx.x * blockDim.x + threadIdx.x;
    if (i >= n4) return;
    float4 v = x[i];
    __half2* p = reinterpret_cast<__half2*>(y + (size_t)i * 4);
    p[0] = __floats2half2_rn(v.x, v.y);
    p[1] = __floats2half2_rn(v.z, v.w);
}

// ---------------------------------------------------------------------------
// Wq/Wk fp32 -> fp16 TRANSPOSED (smem tiled); z selects which weight
// ---------------------------------------------------------------------------
__global__ void __launch_bounds__(256)
tconv_k(const float* __restrict__ wq, const float* __restrict__ wk,
        __half* __restrict__ wqT, __half* __restrict__ wkT)
{
    __shared__ float tile[32][33];
    const float* src = blockIdx.z ? wk : wq;
    __half* dst = blockIdx.z ? wkT : wqT;
    int x0 = blockIdx.x * 32;
    int y0 = blockIdx.y * 32;
    int tx = threadIdx.x & 31, ty = threadIdx.x >> 5;
#pragma unroll
    for (int i = 0; i < 4; i++)
        tile[ty + i * 8][tx] = src[(size_t)(y0 + ty + i * 8) * DIM + x0 + tx];
    __syncthreads();
#pragma unroll
    for (int i = 0; i < 4; i++)
        dst[(size_t)(x0 + ty + i * 8) * HDIM + y0 + tx] =
            __float2half_rn(tile[tx][ty + i * 8]);
}

// ---------------------------------------------------------------------------
extern "C" void kernel_launch(void* const* d_in, const int* in_sizes, int n_in,
                              void* d_out, int out_size)
{
    const float* img = (const float*)d_in[0];   // [N_IMG, DIM]
    const float* txt = (const float*)d_in[1];   // [N_TXT, DIM]
    const float* WQ  = (const float*)d_in[2];   // [HDIM, DIM]
    const float* WK  = (const float*)d_in[3];   // [HDIM, DIM]
    const float* WV  = (const float*)d_in[4];   // [DIM, DIM]
    float* out = (float*)d_out;                 // [N_IMG, DIM]

    static bool init_done = false;
    static cudaStream_t sv = nullptr, si = nullptr;
    static cudaEvent_t ev_fork = nullptr, ev_txt = nullptr, ev_join = nullptr, ev_img = nullptr;
    if (!init_done) {
        cudaFuncSetAttribute(hgemm128,   cudaFuncAttributeMaxDynamicSharedMemorySize, H_SMEM);
        cudaFuncSetAttribute(hgemm64<1>, cudaFuncAttributeMaxDynamicSharedMemorySize, S64_SMEM);
        cudaFuncSetAttribute(hgemm64<2>, cudaFuncAttributeMaxDynamicSharedMemorySize, S64_SMEM);
        cudaFuncSetAttribute(hgemm64<3>, cudaFuncAttributeMaxDynamicSharedMemorySize, S64_SMEM);
        cudaStreamCreateWithFlags(&sv, cudaStreamNonBlocking);
        cudaStreamCreateWithFlags(&si, cudaStreamNonBlocking);
        cudaEventCreateWithFlags(&ev_fork, cudaEventDisableTiming);
        cudaEventCreateWithFlags(&ev_txt,  cudaEventDisableTiming);
        cudaEventCreateWithFlags(&ev_join, cudaEventDisableTiming);
        cudaEventCreateWithFlags(&ev_img,  cudaEventDisableTiming);
        init_done = true;
    }

    __half *img16, *txt16, *wqT16, *wkT16, *m1t16, *wv16, *q16, *vt16, *p16;
    float *rowsum;
    cudaGetSymbolAddress((void**)&img16, g_img16);
    cudaGetSymbolAddress((void**)&txt16, g_txt16);
    cudaGetSymbolAddress((void**)&wqT16, g_wqT16);
    cudaGetSymbolAddress((void**)&wkT16, g_wkT16);
    cudaGetSymbolAddress((void**)&m1t16, g_m1t16);
    cudaGetSymbolAddress((void**)&wv16, g_wv16);
    cudaGetSymbolAddress((void**)&q16, g_q16);
    cudaGetSymbolAddress((void**)&vt16, g_vt16);
    cudaGetSymbolAddress((void**)&p16, g_p16);
    cudaGetSymbolAddress((void**)&rowsum, g_rowsum);

    // ---- fork ----
    cudaEventRecord(ev_fork, 0);
    cudaStreamWaitEvent(sv, ev_fork, 0);
    cudaStreamWaitEvent(si, ev_fork, 0);

    // side stream si: img conv + rowsum zero (overlaps tconv + M1 on main)
    conv_img_k<<<(CN_MAIN + 255) / 256, 256, 0, si>>>(
        (const float4*)img, img16, (float4*)rowsum);
    cudaEventRecord(ev_img, si);

    // side stream sv: txt conv + V chain
    conv16_k<<<(N_TXT * DIM / 4 + 255) / 256, 256, 0, sv>>>(
        (const float4*)txt, txt16, N_TXT * DIM / 4);
    cudaEventRecord(ev_txt, sv);            // main's QK needs txt16
    conv16_k<<<(DIM * DIM / 4 + 255) / 256, 256, 0, sv>>>(
        (const float4*)WV, wv16, DIM * DIM / 4);
    // Vt = WV @ txt^T -> fp16 [DIM, N_TXT]
    hgemm64<1><<<dim3(N_TXT / 128, DIM / 64), 256, S64_SMEM, sv>>>(
        wv16, txt16, nullptr, vt16, nullptr, DIM, N_TXT, DIM);
    cudaEventRecord(ev_join, sv);

    // ---- main stream: weight transposes + M1 ----
    tconv_k<<<dim3(DIM / 32, HDIM / 32, 2), 256>>>(WQ, WK, wqT16, wkT16);
    // M1T = wkT @ wqT^T  [DIM, DIM]
    hgemm128<<<dim3(DIM / 128, DIM / 128), 256, H_SMEM>>>(
        wkT16, wqT16, m1t16, DIM, DIM, HDIM);

    // A2 needs img16
    cudaStreamWaitEvent(0, ev_img, 0);
    // A2 = img @ M1 = img @ m1t^T -> fp16 [N_IMG, DIM]
    hgemm64<1><<<dim3(DIM / 128, N_IMG / 64), 256, S64_SMEM>>>(
        img16, m1t16, nullptr, q16, nullptr, N_IMG, DIM, DIM);

    // QK needs txt16 from side stream
    cudaStreamWaitEvent(0, ev_txt, 0);
    // P~ = exp(A2@txt^T / 32 - 8) -> fp16, rowsum via atomics
    hgemm64<2><<<dim3(N_TXT / 128, N_IMG / 64), 256, S64_SMEM>>>(
        q16, txt16, nullptr, p16, rowsum, N_IMG, N_TXT, DIM);

    // ---- join: PV needs vt16 ----
    cudaStreamWaitEvent(0, ev_join, 0);
    // out = (P~ @ Vt^T) / rowsum[row] -> fp32
    hgemm64<3><<<dim3(DIM / 128, N_IMG / 64), 256, S64_SMEM>>>(
        p16, vt16, out, nullptr, rowsum, N_IMG, DIM, N_TXT);
}

// round 17
// speedup vs baseline: 1.0809x; 1.0809x over previous
#include <cuda_runtime.h>
#include <cuda_fp16.h>
#include <cstdint>

#define N_IMG 8192
#define N_TXT 8192
#define DIM   1024
#define HDIM  1024

// ---------------------------------------------------------------------------
// Device scratch (no allocations allowed)
// ---------------------------------------------------------------------------
__device__ __align__(1024) __half g_img16[(size_t)N_IMG * DIM];
__device__ __align__(1024) __half g_txt16[(size_t)N_TXT * DIM];
__device__ __align__(1024) __half g_wqT16[(size_t)DIM * HDIM];     // Wq^T [D,H]
__device__ __align__(1024) __half g_wkT16[(size_t)DIM * HDIM];     // Wk^T [D,H]
__device__ __align__(1024) __half g_m1t16[(size_t)DIM * DIM];      // (Wq^T Wk)^T
__device__ __align__(1024) __half g_wv16 [(size_t)DIM * DIM];      // fp16 WV
__device__ __align__(1024) __half g_q16 [(size_t)N_IMG * HDIM];    // A2 = img @ M1
__device__ __align__(1024) __half g_vt16[(size_t)DIM * N_TXT];
__device__ __align__(1024) __half g_p16 [(size_t)N_IMG * N_TXT];   // 128 MB
__device__ __align__(1024) float  g_rowsum[N_IMG];

// exp constants: exp(s*0.03125 - 8) = exp2(acc*c1 + c2)
#define EXP_C1 0.04508422f      // 0.03125 * log2(e)
#define EXP_C2 -11.54156036f    // -8 * log2(e)

// ---------------------------------------------------------------------------
// Portable PTX helpers
// ---------------------------------------------------------------------------
__device__ __forceinline__ uint32_t smem_to_u32(const void* p) {
    uint32_t a;
    asm("{ .reg .u64 t; cvta.to.shared.u64 t, %1; cvt.u32.u64 %0, t; }" : "=r"(a) : "l"(p));
    return a;
}
__device__ __forceinline__ void ldmatrix_x4(uint32_t* r, uint32_t addr) {
    asm volatile("ldmatrix.sync.aligned.m8n8.x4.shared.b16 {%0,%1,%2,%3}, [%4];"
        : "=r"(r[0]), "=r"(r[1]), "=r"(r[2]), "=r"(r[3]) : "r"(addr));
}
__device__ __forceinline__ void mma_fp16(float* c, const uint32_t* a, uint32_t b0, uint32_t b1) {
    asm volatile("mma.sync.aligned.m16n8k16.row.col.f32.f16.f16.f32 "
        "{%0,%1,%2,%3}, {%4,%5,%6,%7}, {%8,%9}, {%0,%1,%2,%3};"
        : "+f"(c[0]), "+f"(c[1]), "+f"(c[2]), "+f"(c[3])
        : "r"(a[0]), "r"(a[1]), "r"(a[2]), "r"(a[3]), "r"(b0), "r"(b1));
}
#define CP_ASYNC16(dst, src) \
    asm volatile("cp.async.cg.shared.global [%0], [%1], 16;" :: "r"(dst), "l"(src) : "memory")
#define CP_COMMIT() asm volatile("cp.async.commit_group;" ::: "memory")
#define CP_WAIT1()  asm volatile("cp.async.wait_group 1;" ::: "memory")

// ===========================================================================
// Tile loaders (K-major fp16, 64 cols = 128 B/row, swizzle c ^= r&7)
// ===========================================================================
__device__ __forceinline__ void load_tile64h(uint32_t dst, const __half* __restrict__ src,
                                             int ldK, int tid) {
#pragma unroll
    for (int i = 0; i < 4; i++) {
        int idx = tid + i * 256;
        int r = idx >> 3, c = idx & 7;
        int sc = c ^ (r & 7);
        CP_ASYNC16(dst + r * 128 + (sc << 4), src + (size_t)r * ldK + c * 8);
    }
}
__device__ __forceinline__ void load_tile64x64h(uint32_t dst, const __half* __restrict__ src,
                                                int ldK, int tid) {
#pragma unroll
    for (int i = 0; i < 2; i++) {
        int idx = tid + i * 256;
        int r = idx >> 3, c = idx & 7;
        int sc = c ^ (r & 7);
        CP_ASYNC16(dst + r * 128 + (sc << 4), src + (size_t)r * ldK + c * 8);
    }
}

// ===========================================================================
// Kernel A: 128x128 fp16 GEMM (C fp16) — M1 only (tiny)
// ===========================================================================
constexpr int H_TILE = 16384;
constexpr int H_OFF_A = 0, H_OFF_B = H_TILE;
constexpr int H_STG = 2 * H_TILE;
constexpr int H_NSTAGE = 3;
constexpr int H_SMEM = H_NSTAGE * H_STG;     // 96 KB

__global__ void __launch_bounds__(256, 1)
hgemm128(const __half* __restrict__ A, const __half* __restrict__ B,
         __half* __restrict__ Ch, int M, int N, int K)
{
    extern __shared__ __align__(1024) char smem[];
    const uint32_t sb = smem_to_u32(smem);
    const int tid  = threadIdx.x;
    const int lane = tid & 31;
    const int wid  = tid >> 5;
    const int wm   = wid & 1;
    const int wn   = wid >> 1;
    const int m0   = blockIdx.y * 128, n0 = blockIdx.x * 128;

    const __half* Ar = A + (size_t)m0 * K;
    const __half* Br = B + (size_t)n0 * K;

    float acc[4][4][4];
#pragma unroll
    for (int i = 0; i < 4; i++)
#pragma unroll
        for (int j = 0; j < 4; j++)
#pragma unroll
            for (int t = 0; t < 4; t++) acc[i][j][t] = 0.f;

    const int NK = K >> 6;

#pragma unroll
    for (int i = 0; i < H_NSTAGE - 1; i++) {
        if (i < NK) {
            uint32_t st = sb + i * H_STG;
            int ko = i * 64;
            load_tile64h(st + H_OFF_A, Ar + ko, K, tid);
            load_tile64h(st + H_OFF_B, Br + ko, K, tid);
        }
        CP_COMMIT();
    }

    const int lr = lane & 15;
    const int lc = lane >> 4;

    for (int k = 0; k < NK; k++) {
        CP_WAIT1();
        __syncthreads();

        int kn = k + H_NSTAGE - 1;
        if (kn < NK) {
            uint32_t st = sb + (kn % H_NSTAGE) * H_STG;
            int ko = kn * 64;
            load_tile64h(st + H_OFF_A, Ar + ko, K, tid);
            load_tile64h(st + H_OFF_B, Br + ko, K, tid);
        }
        CP_COMMIT();

        const uint32_t s = sb + (k % H_NSTAGE) * H_STG;
#pragma unroll
        for (int ks = 0; ks < 4; ks++) {
            uint32_t af[4][4], bfr[2][4];
#pragma unroll
            for (int mi = 0; mi < 4; mi++) {
                int r = wm * 64 + mi * 16 + lr;
                int c = ks * 2 + lc;
                int sc = c ^ (r & 7);
                ldmatrix_x4(af[mi], s + H_OFF_A + r * 128 + (sc << 4));
            }
#pragma unroll
            for (int nj = 0; nj < 2; nj++) {
                int r = wn * 32 + nj * 16 + lr;
                int c = ks * 2 + lc;
                int sc = c ^ (r & 7);
                ldmatrix_x4(bfr[nj], s + H_OFF_B + r * 128 + (sc << 4));
            }
#pragma unroll
            for (int mi = 0; mi < 4; mi++)
#pragma unroll
                for (int ni = 0; ni < 4; ni++) {
                    int nj = ni >> 1, hl = ni & 1;
                    mma_fp16(acc[mi][ni], af[mi], bfr[nj][hl], bfr[nj][2 + hl]);
                }
        }
    }

    const int er = (lane >> 2);
    const int ec = (lane & 3) * 2;
#pragma unroll
    for (int mi = 0; mi < 4; mi++)
#pragma unroll
        for (int ni = 0; ni < 4; ni++) {
            int row = m0 + wm * 64 + mi * 16 + er;
            int col = n0 + wn * 32 + ni * 8 + ec;
#pragma unroll
            for (int h = 0; h < 2; h++) {
                size_t off = (size_t)(row + 8 * h) * N + col;
                *reinterpret_cast<__half2*>(Ch + off) =
                    __floats2half2_rn(acc[mi][ni][2 * h], acc[mi][ni][2 * h + 1]);
            }
        }
}

// ===========================================================================
// Kernel B: 64x128 fp16 GEMM, 3 CTAs/SM, 3 stages, precomputed frag offsets
//   MODE 1: C fp16 (A2, Vt);  MODE 2: exp epilogue (QK);  MODE 3: /rowsum (PV)
// ===========================================================================
constexpr int S64_OFF_A = 0, S64_OFF_B = 8192;    // A 8 KB, B 16 KB
constexpr int S64_STG = 24576;
constexpr int S64_NSTAGE = 3;
constexpr int S64_SMEM = S64_NSTAGE * S64_STG;    // 72 KB (3 CTAs: 216 KB/SM)

template <int MODE>
__global__ void __launch_bounds__(256, 3)
hgemm64(const __half* __restrict__ A, const __half* __restrict__ B,
        float* __restrict__ Cf, __half* __restrict__ Ch,
        float* __restrict__ rowsum, int M, int N, int K)
{
    extern __shared__ __align__(1024) char smem[];
    const uint32_t sb = smem_to_u32(smem);
    const int tid  = threadIdx.x;
    const int lane = tid & 31;
    const int wid  = tid >> 5;
    const int wm   = wid & 1;     // 2 warp rows (32 rows each)
    const int wn   = wid >> 1;    // 4 warp cols (32 cols each)
    const int m0   = blockIdx.y * 64, n0 = blockIdx.x * 128;

    // rolling global pointers (advance by 64 each chunk)
    const __half* Aw = A + (size_t)m0 * K;
    const __half* Bw = B + (size_t)n0 * K;

    float acc[2][4][4];
#pragma unroll
    for (int i = 0; i < 2; i++)
#pragma unroll
        for (int j = 0; j < 4; j++)
#pragma unroll
            for (int t = 0; t < 4; t++) acc[i][j][t] = 0.f;

    const int NK = K >> 6;

    // prologue: stages 0,1 in flight
#pragma unroll
    for (int i = 0; i < S64_NSTAGE - 1; i++) {
        if (i < NK) {
            uint32_t st = sb + i * S64_STG;
            load_tile64x64h(st + S64_OFF_A, Aw, K, tid);
            load_tile64h(st + S64_OFF_B, Bw, K, tid);
            Aw += 64; Bw += 64;
        }
        CP_COMMIT();
    }

    const int lr = lane & 15;
    const int lc = lane >> 4;
    // precomputed per-ks swizzled fragment offsets (relative to stage base)
    const uint32_t arow0 = (uint32_t)(wm * 32 + lr) * 128 + S64_OFF_A;
    const uint32_t brow0 = (uint32_t)(wn * 32 + lr) * 128 + S64_OFF_B;
    const int arb0 = (wm * 32 + lr) & 7;
    const int brb0 = (wn * 32 + lr) & 7;
    uint32_t off_a[4], off_b[4];
#pragma unroll
    for (int ks = 0; ks < 4; ks++) {
        const int c = ks * 2 + lc;
        off_a[ks] = arow0 + (uint32_t)((c ^ arb0) << 4);
        off_b[ks] = brow0 + (uint32_t)((c ^ brb0) << 4);
    }

    // rolling smem stage offsets
    uint32_t rd = sb;                          // stage being computed
    uint32_t wr = sb + 2 * S64_STG;            // stage being filled
    const uint32_t send = sb + 3 * S64_STG;

    for (int k = 0; k < NK; k++) {
        CP_WAIT1();
        __syncthreads();

        if (k + S64_NSTAGE - 1 < NK) {
            load_tile64x64h(wr + S64_OFF_A, Aw, K, tid);
            load_tile64h(wr + S64_OFF_B, Bw, K, tid);
            Aw += 64; Bw += 64;
        }
        CP_COMMIT();
        wr += S64_STG; if (wr == send) wr = sb;

#pragma unroll
        for (int ks = 0; ks < 4; ks++) {
            uint32_t af[2][4], bfr[2][4];
            ldmatrix_x4(af[0], rd + off_a[ks]);
            ldmatrix_x4(af[1], rd + off_a[ks] + 16 * 128);
            ldmatrix_x4(bfr[0], rd + off_b[ks]);
            ldmatrix_x4(bfr[1], rd + off_b[ks] + 16 * 128);
#pragma unroll
            for (int mi = 0; mi < 2; mi++)
#pragma unroll
                for (int ni = 0; ni < 4; ni++) {
                    int nj = ni >> 1, hl = ni & 1;
                    mma_fp16(acc[mi][ni], af[mi], bfr[nj][hl], bfr[nj][2 + hl]);
                }
        }
        rd += S64_STG; if (rd == send) rd = sb;
    }

    const int er = (lane >> 2);
    const int ec = (lane & 3) * 2;
#pragma unroll
    for (int mi = 0; mi < 2; mi++) {
        float rsum[2] = {0.f, 0.f};
        float rinv[2];
        if (MODE == 3) {
            rinv[0] = 1.0f / rowsum[m0 + wm * 32 + mi * 16 + er];
            rinv[1] = 1.0f / rowsum[m0 + wm * 32 + mi * 16 + er + 8];
        }
#pragma unroll
        for (int ni = 0; ni < 4; ni++) {
            int row = m0 + wm * 32 + mi * 16 + er;
            int col = n0 + wn * 32 + ni * 8 + ec;
#pragma unroll
            for (int h = 0; h < 2; h++) {
                float v0 = acc[mi][ni][2 * h + 0];
                float v1 = acc[mi][ni][2 * h + 1];
                size_t off = (size_t)(row + 8 * h) * N + col;
                if (MODE == 1) {
                    *reinterpret_cast<__half2*>(Ch + off) = __floats2half2_rn(v0, v1);
                } else if (MODE == 2) {
                    float e0 = exp2f(fmaf(v0, EXP_C1, EXP_C2));
                    float e1 = exp2f(fmaf(v1, EXP_C1, EXP_C2));
                    *reinterpret_cast<__half2*>(Ch + off) = __floats2half2_rn(e0, e1);
                    rsum[h] += e0 + e1;
                } else {   // MODE 3
                    *reinterpret_cast<float2*>(Cf + off) =
                        make_float2(v0 * rinv[h], v1 * rinv[h]);
                }
            }
        }
        if (MODE == 2) {
#pragma unroll
            for (int h = 0; h < 2; h++) {
                float v = rsum[h];
                v += __shfl_xor_sync(0xFFFFFFFFu, v, 1);
                v += __shfl_xor_sync(0xFFFFFFFFu, v, 2);
                if ((lane & 3) == 0)
                    atomicAdd(&rowsum[m0 + wm * 32 + mi * 16 + er + 8 * h], v);
            }
        }
    }
}

// ---------------------------------------------------------------------------
// img fp32->fp16 + rowsum zeroing
// ---------------------------------------------------------------------------
constexpr int CN_IMG = N_IMG * DIM / 4;
constexpr int CN_RS  = N_IMG / 4;
constexpr int CN_MAIN = CN_IMG + CN_RS;

__global__ void __launch_bounds__(256)
conv_img_k(const float4* __restrict__ img, __half* __restrict__ img16,
           float4* __restrict__ rowsum)
{
    int i = blockIdx.x * blockDim.x + threadIdx.x;
    if (i < CN_IMG) {
        float4 v = img[i];
        __half2* p = reinterpret_cast<__half2*>(img16 + (size_t)i * 4);
        p[0] = __floats2half2_rn(v.x, v.y);
        p[1] = __floats2half2_rn(v.z, v.w);
    } else if (i - CN_IMG < CN_RS) {
        rowsum[i - CN_IMG] = make_float4(0.f, 0.f, 0.f, 0.f);
    }
}

__global__ void __launch_bounds__(256)
conv16_k(const float4* __restrict__ x, __half* __restrict__ y, int n4)
{
    int i = blockIdx.x * blockDim.x + threadIdx.x;
    if (i >= n4) return;
    float4 v = x[i];
    __half2* p = reinterpret_cast<__half2*>(y + (size_t)i * 4);
    p[0] = __floats2half2_rn(v.x, v.y);
    p[1] = __floats2half2_rn(v.z, v.w);
}

// ---------------------------------------------------------------------------
// Wq/Wk fp32 -> fp16 TRANSPOSED (smem tiled); z selects which weight
// ---------------------------------------------------------------------------
__global__ void __launch_bounds__(256)
tconv_k(const float* __restrict__ wq, const float* __restrict__ wk,
        __half* __restrict__ wqT, __half* __restrict__ wkT)
{
    __shared__ float tile[32][33];
    const float* src = blockIdx.z ? wk : wq;
    __half* dst = blockIdx.z ? wkT : wqT;
    int x0 = blockIdx.x * 32;
    int y0 = blockIdx.y * 32;
    int tx = threadIdx.x & 31, ty = threadIdx.x >> 5;
#pragma unroll
    for (int i = 0; i < 4; i++)
        tile[ty + i * 8][tx] = src[(size_t)(y0 + ty + i * 8) * DIM + x0 + tx];
    __syncthreads();
#pragma unroll
    for (int i = 0; i < 4; i++)
        dst[(size_t)(x0 + ty + i * 8) * HDIM + y0 + tx] =
            __float2half_rn(tile[tx][ty + i * 8]);
}

// ---------------------------------------------------------------------------
extern "C" void kernel_launch(void* const* d_in, const int* in_sizes, int n_in,
                              void* d_out, int out_size)
{
    const float* img = (const float*)d_in[0];   // [N_IMG, DIM]
    const float* txt = (const float*)d_in[1];   // [N_TXT, DIM]
    const float* WQ  = (const float*)d_in[2];   // [HDIM, DIM]
    const float* WK  = (const float*)d_in[3];   // [HDIM, DIM]
    const float* WV  = (const float*)d_in[4];   // [DIM, DIM]
    float* out = (float*)d_out;                 // [N_IMG, DIM]

    static bool init_done = false;
    static cudaStream_t sv = nullptr, si = nullptr;
    static cudaEvent_t ev_fork = nullptr, ev_txt = nullptr, ev_join = nullptr, ev_img = nullptr;
    if (!init_done) {
        cudaFuncSetAttribute(hgemm128,   cudaFuncAttributeMaxDynamicSharedMemorySize, H_SMEM);
        cudaFuncSetAttribute(hgemm64<1>, cudaFuncAttributeMaxDynamicSharedMemorySize, S64_SMEM);
        cudaFuncSetAttribute(hgemm64<2>, cudaFuncAttributeMaxDynamicSharedMemorySize, S64_SMEM);
        cudaFuncSetAttribute(hgemm64<3>, cudaFuncAttributeMaxDynamicSharedMemorySize, S64_SMEM);
        cudaStreamCreateWithFlags(&sv, cudaStreamNonBlocking);
        cudaStreamCreateWithFlags(&si, cudaStreamNonBlocking);
        cudaEventCreateWithFlags(&ev_fork, cudaEventDisableTiming);
        cudaEventCreateWithFlags(&ev_txt,  cudaEventDisableTiming);
        cudaEventCreateWithFlags(&ev_join, cudaEventDisableTiming);
        cudaEventCreateWithFlags(&ev_img,  cudaEventDisableTiming);
        init_done = true;
    }

    __half *img16, *txt16, *wqT16, *wkT16, *m1t16, *wv16, *q16, *vt16, *p16;
    float *rowsum;
    cudaGetSymbolAddress((void**)&img16, g_img16);
    cudaGetSymbolAddress((void**)&txt16, g_txt16);
    cudaGetSymbolAddress((void**)&wqT16, g_wqT16);
    cudaGetSymbolAddress((void**)&wkT16, g_wkT16);
    cudaGetSymbolAddress((void**)&m1t16, g_m1t16);
    cudaGetSymbolAddress((void**)&wv16, g_wv16);
    cudaGetSymbolAddress((void**)&q16, g_q16);
    cudaGetSymbolAddress((void**)&vt16, g_vt16);
    cudaGetSymbolAddress((void**)&p16, g_p16);
    cudaGetSymbolAddress((void**)&rowsum, g_rowsum);

    // ---- fork ----
    cudaEventRecord(ev_fork, 0);
    cudaStreamWaitEvent(sv, ev_fork, 0);
    cudaStreamWaitEvent(si, ev_fork, 0);

    // side stream si: img conv + rowsum zero (overlaps tconv + M1 on main)
    conv_img_k<<<(CN_MAIN + 255) / 256, 256, 0, si>>>(
        (const float4*)img, img16, (float4*)rowsum);
    cudaEventRecord(ev_img, si);

    // side stream sv: txt conv + V chain
    conv16_k<<<(N_TXT * DIM / 4 + 255) / 256, 256, 0, sv>>>(
        (const float4*)txt, txt16, N_TXT * DIM / 4);
    cudaEventRecord(ev_txt, sv);            // main's QK needs txt16
    conv16_k<<<(DIM * DIM / 4 + 255) / 256, 256, 0, sv>>>(
        (const float4*)WV, wv16, DIM * DIM / 4);
    // Vt = WV @ txt^T -> fp16 [DIM, N_TXT]
    hgemm64<1><<<dim3(N_TXT / 128, DIM / 64), 256, S64_SMEM, sv>>>(
        wv16, txt16, nullptr, vt16, nullptr, DIM, N_TXT, DIM);
    cudaEventRecord(ev_join, sv);

    // ---- main stream: weight transposes + M1 ----
    tconv_k<<<dim3(DIM / 32, HDIM / 32, 2), 256>>>(WQ, WK, wqT16, wkT16);
    // M1T = wkT @ wqT^T  [DIM, DIM]
    hgemm128<<<dim3(DIM / 128, DIM / 128), 256, H_SMEM>>>(
        wkT16, wqT16, m1t16, DIM, DIM, HDIM);

    // A2 needs img16
    cudaStreamWaitEvent(0, ev_img, 0);
    // A2 = img @ M1 = img @ m1t^T -> fp16 [N_IMG, DIM]
    hgemm64<1><<<dim3(DIM / 128, N_IMG / 64), 256, S64_SMEM>>>(
        img16, m1t16, nullptr, q16, nullptr, N_IMG, DIM, DIM);

    // QK needs txt16 from side stream
    cudaStreamWaitEvent(0, ev_txt, 0);
    // P~ = exp(A2@txt^T / 32 - 8) -> fp16, rowsum via atomics
    hgemm64<2><<<dim3(N_TXT / 128, N_IMG / 64), 256, S64_SMEM>>>(
        q16, txt16, nullptr, p16, rowsum, N_IMG, N_TXT, DIM);

    // ---- join: PV needs vt16 ----
    cudaStreamWaitEvent(0, ev_join, 0);
    // out = (P~ @ Vt^T) / rowsum[row] -> fp32
    hgemm64<3><<<dim3(DIM / 128, N_IMG / 64), 256, S64_SMEM>>>(
        p16, vt16, out, nullptr, rowsum, N_IMG, DIM, N_TXT);
}